// round 12
// baseline (speedup 1.0000x reference)
#include <cuda_runtime.h>

#define ND 128
#define TE 128
#define MAXN 50000

typedef unsigned long long ull;

__device__ __align__(256) float g_P[MAXN * ND];
__device__ __align__(256) float g_agg[MAXN * ND];
__device__ __align__(256) float g_H2[MAXN * ND];

__device__ __forceinline__ ull pack2(float x, float y) {
    ull r; asm("mov.b64 %0, {%1, %2};" : "=l"(r) : "f"(x), "f"(y)); return r;
}
__device__ __forceinline__ void unpack2(ull v, float& x, float& y) {
    asm("mov.b64 {%0, %1}, %2;" : "=f"(x), "=f"(y) : "l"(v));
}
__device__ __forceinline__ void fma2(ull& acc, ull a, ull b) {
    asm("fma.rn.f32x2 %0, %1, %2, %0;" : "+l"(acc) : "l"(a), "l"(b));
}
__device__ __forceinline__ float lrelu(float x) { return x >= 0.f ? x : 0.2f * x; }

// 4 fma2 on one 8-col group; weights via warp-uniform global broadcast (L1-hit)
__device__ __forceinline__ void fma_row8g(ull* acc, ull a2, const float* __restrict__ wrow) {
    const ulonglong2* wr = (const ulonglong2*)wrow;
    ulonglong2 w0 = __ldg(wr), w1 = __ldg(wr + 1);
    fma2(acc[0], a2, w0.x); fma2(acc[1], a2, w0.y);
    fma2(acc[2], a2, w1.x); fma2(acc[3], a2, w1.y);
}

// ---------------------------------------------------------------------------
__global__ void zero_kernel(int n4) {
    int i = blockIdx.x * blockDim.x + threadIdx.x;
    if (i < n4) ((float4*)g_agg)[i] = make_float4(0.f, 0.f, 0.f, 0.f);
}

// ---------------------------------------------------------------------------
// P = node_feats @ msg_w1[0:128,:]. 128 rows/block, 512 thr (4 rows x 8 cols)
__global__ __launch_bounds__(512, 2) void p_kernel(
    const float* __restrict__ nf, const float* __restrict__ w1, int N)
{
    extern __shared__ float sm[];
    float* sa = sm;  // 128 k * 132 (k-major)
    int tid = threadIdx.x;
    int n0 = blockIdx.x * 128;

    for (int i = tid; i < 4096; i += 512) {
        int r = i & 127, j = i >> 7, gn = n0 + r;
        float4 v = (gn < N) ? ((const float4*)nf)[(size_t)gn * 32 + j]
                            : make_float4(0.f, 0.f, 0.f, 0.f);
        sa[(4 * j + 0) * 132 + r] = v.x;
        sa[(4 * j + 1) * 132 + r] = v.y;
        sa[(4 * j + 2) * 132 + r] = v.z;
        sa[(4 * j + 3) * 132 + r] = v.w;
    }
    __syncthreads();

    int q = tid & 31, c0 = (tid >> 5) * 8, rb = 4 * q;
    ull acc[16];
#pragma unroll
    for (int i = 0; i < 16; i++) acc[i] = pack2(0.f, 0.f);
#pragma unroll 2
    for (int k = 0; k < 128; k++) {
        float4 a = *(float4*)(sa + k * 132 + rb);
        const float* wrow = w1 + k * ND + c0;
        fma_row8g(acc + 0,  pack2(a.x, a.x), wrow);
        fma_row8g(acc + 4,  pack2(a.y, a.y), wrow);
        fma_row8g(acc + 8,  pack2(a.z, a.z), wrow);
        fma_row8g(acc + 12, pack2(a.w, a.w), wrow);
    }
#pragma unroll
    for (int j = 0; j < 4; j++) {
        int gn = n0 + rb + j;
        if (gn < N) {
            float4* pr = (float4*)(g_P + (size_t)gn * ND + c0);
#pragma unroll
            for (int i = 0; i < 2; i++) {
                float x, y, z, w_;
                unpack2(acc[j * 4 + 2 * i], x, y);
                unpack2(acc[j * 4 + 2 * i + 1], z, w_);
                pr[i] = make_float4(x, y, z, w_);
            }
        }
    }
}

// ---------------------------------------------------------------------------
// Fused edge kernel. 128 edges/block, 512 thr (4 edges x 8 cols).
__global__ __launch_bounds__(512, 2) void edge_kernel(
    const float* __restrict__ ef,
    const float* __restrict__ w1, const float* __restrict__ b1,
    const float* __restrict__ w2, const float* __restrict__ b2,
    const int* __restrict__ eidx, int N, int E)
{
    extern __shared__ float sm[];
    float* seft = sm;                 // 64 k * 132 = 8448  (k-major)
    float* sht  = sm + 8448;          // 128 k * 132 = 16896 (k-major)
    int*   ssrc = (int*)(sm + 25344); // 128
    int*   sdst = ssrc + 128;         // 128

    int tid = threadIdx.x;
    int e0 = blockIdx.x * TE;
    const float* w1e = w1 + 128 * ND;

    if (tid < TE) {
        int ge = e0 + tid;
        if (ge < E) {
            int s = eidx[ge], d = eidx[E + ge];
            ssrc[tid] = ((unsigned)s < (unsigned)N) ? s : -1;
            sdst[tid] = ((unsigned)d < (unsigned)N) ? d : 0;
        } else { ssrc[tid] = -1; sdst[tid] = 0; }
    }
    for (int i = tid; i < 2048; i += 512) {
        int r = i & 127, j = i >> 7, ge = e0 + r;
        float4 v = (ge < E) ? ((const float4*)ef)[(size_t)ge * 16 + j]
                            : make_float4(0.f, 0.f, 0.f, 0.f);
        seft[(4 * j + 0) * 132 + r] = v.x;
        seft[(4 * j + 1) * 132 + r] = v.y;
        seft[(4 * j + 2) * 132 + r] = v.z;
        seft[(4 * j + 3) * 132 + r] = v.w;
    }
    __syncthreads();

    int q = tid & 31, c0 = (tid >> 5) * 8, eb = 4 * q;

    // phase A: h = lrelu(P[dst] + ef @ w1e + b1), K=64
    ull acc[16];
#pragma unroll
    for (int i = 0; i < 16; i++) acc[i] = pack2(0.f, 0.f);
#pragma unroll 2
    for (int k = 0; k < 64; k++) {
        float4 a = *(float4*)(seft + k * 132 + eb);
        const float* wrow = w1e + k * ND + c0;
        fma_row8g(acc + 0,  pack2(a.x, a.x), wrow);
        fma_row8g(acc + 4,  pack2(a.y, a.y), wrow);
        fma_row8g(acc + 8,  pack2(a.z, a.z), wrow);
        fma_row8g(acc + 12, pack2(a.w, a.w), wrow);
    }
    float hh[4][8];
    {
        const float4* br = (const float4*)(b1 + c0);
        float4 bb0 = __ldg(br), bb1 = __ldg(br + 1);
#pragma unroll
        for (int j = 0; j < 4; j++) {
            int d = sdst[eb + j];
            const float4* pr = (const float4*)(g_P + (size_t)d * ND + c0);
            float4 p0 = pr[0], p1 = pr[1];
            float x, y, z, w_;
            unpack2(acc[j * 4 + 0], x, y);
            unpack2(acc[j * 4 + 1], z, w_);
            hh[j][0] = lrelu(x + p0.x + bb0.x);
            hh[j][1] = lrelu(y + p0.y + bb0.y);
            hh[j][2] = lrelu(z + p0.z + bb0.z);
            hh[j][3] = lrelu(w_ + p0.w + bb0.w);
            unpack2(acc[j * 4 + 2], x, y);
            unpack2(acc[j * 4 + 3], z, w_);
            hh[j][4] = lrelu(x + p1.x + bb1.x);
            hh[j][5] = lrelu(y + p1.y + bb1.y);
            hh[j][6] = lrelu(z + p1.z + bb1.z);
            hh[j][7] = lrelu(w_ + p1.w + bb1.w);
        }
    }
    // transposed store: sht[c][edge], 4 edges per float4
#pragma unroll
    for (int c = 0; c < 8; c++)
        *(float4*)(sht + (c0 + c) * 132 + eb) =
            make_float4(hh[0][c], hh[1][c], hh[2][c], hh[3][c]);
    __syncthreads();

    // phase B: messages = h @ w2 + b2, K=128, scatter
#pragma unroll
    for (int i = 0; i < 16; i++) acc[i] = pack2(0.f, 0.f);
#pragma unroll 2
    for (int k = 0; k < 128; k++) {
        float4 a = *(float4*)(sht + k * 132 + eb);
        const float* wrow = w2 + k * ND + c0;
        fma_row8g(acc + 0,  pack2(a.x, a.x), wrow);
        fma_row8g(acc + 4,  pack2(a.y, a.y), wrow);
        fma_row8g(acc + 8,  pack2(a.z, a.z), wrow);
        fma_row8g(acc + 12, pack2(a.w, a.w), wrow);
    }
    {
        const float4* br = (const float4*)(b2 + c0);
        float4 bb0 = __ldg(br), bb1 = __ldg(br + 1);
#pragma unroll
        for (int j = 0; j < 4; j++) {
            int s = ssrc[eb + j];
            if (s >= 0) {
                float* ar = g_agg + (size_t)s * ND + c0;
                float x, y, z, w_;
                unpack2(acc[j * 4 + 0], x, y);
                unpack2(acc[j * 4 + 1], z, w_);
                x += bb0.x; y += bb0.y; z += bb0.z; w_ += bb0.w;
                asm volatile("red.global.add.v4.f32 [%0], {%1, %2, %3, %4};"
                    :: "l"(ar), "f"(x), "f"(y), "f"(z), "f"(w_) : "memory");
                unpack2(acc[j * 4 + 2], x, y);
                unpack2(acc[j * 4 + 3], z, w_);
                x += bb1.x; y += bb1.y; z += bb1.z; w_ += bb1.w;
                asm volatile("red.global.add.v4.f32 [%0], {%1, %2, %3, %4};"
                    :: "l"(ar + 4), "f"(x), "f"(y), "f"(z), "f"(w_) : "memory");
            }
        }
    }
}

// ---------------------------------------------------------------------------
// H2 = lrelu([nf, agg] @ upd_w1 + ub1). 64 rows/block, 512 thr (2 rows x 8 cols)
__global__ __launch_bounds__(512, 2) void upd1_kernel(
    const float* __restrict__ nf, const float* __restrict__ w1,
    const float* __restrict__ b1, int N)
{
    extern __shared__ float sm[];
    float* sa = sm;  // 256 k * 68
    int tid = threadIdx.x;
    int n0 = blockIdx.x * 64;

    for (int i = tid; i < 2048; i += 512) {
        int r = i & 63, j = i >> 6, gn = n0 + r;
        float4 v = (gn < N) ? ((const float4*)nf)[(size_t)gn * 32 + j]
                            : make_float4(0.f, 0.f, 0.f, 0.f);
        float4 u = (gn < N) ? ((const float4*)g_agg)[(size_t)gn * 32 + j]
                            : make_float4(0.f, 0.f, 0.f, 0.f);
        sa[(4 * j + 0) * 68 + r] = v.x;
        sa[(4 * j + 1) * 68 + r] = v.y;
        sa[(4 * j + 2) * 68 + r] = v.z;
        sa[(4 * j + 3) * 68 + r] = v.w;
        sa[(128 + 4 * j + 0) * 68 + r] = u.x;
        sa[(128 + 4 * j + 1) * 68 + r] = u.y;
        sa[(128 + 4 * j + 2) * 68 + r] = u.z;
        sa[(128 + 4 * j + 3) * 68 + r] = u.w;
    }
    __syncthreads();

    int q = tid & 31, c0 = (tid >> 5) * 8, rb = 2 * q;
    ull acc[8];
#pragma unroll
    for (int i = 0; i < 8; i++) acc[i] = pack2(0.f, 0.f);
#pragma unroll 4
    for (int k = 0; k < 256; k++) {
        float2 a = *(float2*)(sa + k * 68 + rb);
        const float* wrow = w1 + k * ND + c0;
        fma_row8g(acc + 0, pack2(a.x, a.x), wrow);
        fma_row8g(acc + 4, pack2(a.y, a.y), wrow);
    }
    {
        const float4* br = (const float4*)(b1 + c0);
        float4 bb0 = __ldg(br), bb1 = __ldg(br + 1);
#pragma unroll
        for (int j = 0; j < 2; j++) {
            int gn = n0 + rb + j;
            if (gn < N) {
                float4* hr = (float4*)(g_H2 + (size_t)gn * ND + c0);
                float x, y, z, w_;
                unpack2(acc[j * 4 + 0], x, y);
                unpack2(acc[j * 4 + 1], z, w_);
                hr[0] = make_float4(lrelu(x + bb0.x), lrelu(y + bb0.y),
                                    lrelu(z + bb0.z), lrelu(w_ + bb0.w));
                unpack2(acc[j * 4 + 2], x, y);
                unpack2(acc[j * 4 + 3], z, w_);
                hr[1] = make_float4(lrelu(x + bb1.x), lrelu(y + bb1.y),
                                    lrelu(z + bb1.z), lrelu(w_ + bb1.w));
            }
        }
    }
}

// ---------------------------------------------------------------------------
// out = H2 @ upd_w2 + ub2. 128 rows/block, 512 thr (4 rows x 8 cols)
__global__ __launch_bounds__(512, 2) void upd2_kernel(
    const float* __restrict__ w2, const float* __restrict__ b2,
    float* __restrict__ out, int N)
{
    extern __shared__ float sm[];
    float* sa = sm;  // 128 k * 132
    int tid = threadIdx.x;
    int n0 = blockIdx.x * 128;

    for (int i = tid; i < 4096; i += 512) {
        int r = i & 127, j = i >> 7, gn = n0 + r;
        float4 v = (gn < N) ? ((const float4*)g_H2)[(size_t)gn * 32 + j]
                            : make_float4(0.f, 0.f, 0.f, 0.f);
        sa[(4 * j + 0) * 132 + r] = v.x;
        sa[(4 * j + 1) * 132 + r] = v.y;
        sa[(4 * j + 2) * 132 + r] = v.z;
        sa[(4 * j + 3) * 132 + r] = v.w;
    }
    __syncthreads();

    int q = tid & 31, c0 = (tid >> 5) * 8, rb = 4 * q;
    ull acc[16];
#pragma unroll
    for (int i = 0; i < 16; i++) acc[i] = pack2(0.f, 0.f);
#pragma unroll 2
    for (int k = 0; k < 128; k++) {
        float4 a = *(float4*)(sa + k * 132 + rb);
        const float* wrow = w2 + k * ND + c0;
        fma_row8g(acc + 0,  pack2(a.x, a.x), wrow);
        fma_row8g(acc + 4,  pack2(a.y, a.y), wrow);
        fma_row8g(acc + 8,  pack2(a.z, a.z), wrow);
        fma_row8g(acc + 12, pack2(a.w, a.w), wrow);
    }
    {
        const float4* br = (const float4*)(b2 + c0);
        float4 bb0 = __ldg(br), bb1 = __ldg(br + 1);
#pragma unroll
        for (int j = 0; j < 4; j++) {
            int gn = n0 + rb + j;
            if (gn < N) {
                float4* orow = (float4*)(out + (size_t)gn * ND + c0);
                float x, y, z, w_;
                unpack2(acc[j * 4 + 0], x, y);
                unpack2(acc[j * 4 + 1], z, w_);
                orow[0] = make_float4(x + bb0.x, y + bb0.y, z + bb0.z, w_ + bb0.w);
                unpack2(acc[j * 4 + 2], x, y);
                unpack2(acc[j * 4 + 3], z, w_);
                orow[1] = make_float4(x + bb1.x, y + bb1.y, z + bb1.z, w_ + bb1.w);
            }
        }
    }
}

// ---------------------------------------------------------------------------
extern "C" void kernel_launch(void* const* d_in, const int* in_sizes, int n_in,
                              void* d_out, int out_size)
{
    const float* nf  = (const float*)d_in[0];
    const float* ef  = (const float*)d_in[1];
    const float* mw1 = (const float*)d_in[2];
    const float* mb1 = (const float*)d_in[3];
    const float* mw2 = (const float*)d_in[4];
    const float* mb2 = (const float*)d_in[5];
    const float* uw1 = (const float*)d_in[6];
    const float* ub1 = (const float*)d_in[7];
    const float* uw2 = (const float*)d_in[8];
    const float* ub2 = (const float*)d_in[9];
    const int* eidx  = (const int*)d_in[10];   // int32 (JAX x64 disabled)
    float* out = (float*)d_out;

    int N = in_sizes[0] / ND;
    int E = in_sizes[10] / 2;

    const int P_SM  = 128 * 132 * 4;            // 67584
    const int E_SM  = (25344 + 256) * 4;        // 102400
    const int U1_SM = 256 * 68 * 4;             // 69632
    const int U2_SM = 128 * 132 * 4;            // 67584

    cudaFuncSetAttribute(p_kernel,    cudaFuncAttributeMaxDynamicSharedMemorySize, P_SM);
    cudaFuncSetAttribute(edge_kernel, cudaFuncAttributeMaxDynamicSharedMemorySize, E_SM);
    cudaFuncSetAttribute(upd1_kernel, cudaFuncAttributeMaxDynamicSharedMemorySize, U1_SM);
    cudaFuncSetAttribute(upd2_kernel, cudaFuncAttributeMaxDynamicSharedMemorySize, U2_SM);

    int n4 = (N * ND) / 4;
    zero_kernel<<<(n4 + 255) / 256, 256>>>(n4);
    p_kernel<<<(N + 127) / 128, 512, P_SM>>>(nf, mw1, N);
    edge_kernel<<<(E + TE - 1) / TE, 512, E_SM>>>(ef, mw1, mb1, mw2, mb2, eidx, N, E);
    upd1_kernel<<<(N + 63) / 64, 512, U1_SM>>>(nf, uw1, ub1, N);
    upd2_kernel<<<(N + 127) / 128, 512, U2_SM>>>(uw2, ub2, out, N);
}

// round 13
// speedup vs baseline: 1.0699x; 1.0699x over previous
#include <cuda_runtime.h>

#define ND 128
#define TE 128
#define MAXN 50000

typedef unsigned long long ull;
typedef const ulonglong2* u2p;

__device__ __align__(256) float g_P[MAXN * ND];
__device__ __align__(256) float g_agg[MAXN * ND];
__device__ __align__(256) float g_H2[MAXN * ND];

__device__ __forceinline__ ull pack2(float x, float y) {
    ull r; asm("mov.b64 %0, {%1, %2};" : "=l"(r) : "f"(x), "f"(y)); return r;
}
__device__ __forceinline__ void unpack2(ull v, float& x, float& y) {
    asm("mov.b64 {%0, %1}, %2;" : "=f"(x), "=f"(y) : "l"(v));
}
__device__ __forceinline__ void fma2(ull& acc, ull a, ull b) {
    asm("fma.rn.f32x2 %0, %1, %2, %0;" : "+l"(acc) : "l"(a), "l"(b));
}
__device__ __forceinline__ float lrelu(float x) { return x >= 0.f ? x : 0.2f * x; }

// 4 fma2 on one 8-col group with preloaded weight registers
__device__ __forceinline__ void fma_row8w(ull* acc, ull a2, ulonglong2 wa, ulonglong2 wb) {
    fma2(acc[0], a2, wa.x); fma2(acc[1], a2, wa.y);
    fma2(acc[2], a2, wb.x); fma2(acc[3], a2, wb.y);
}
__device__ __forceinline__ void ldw(const float* wrow, ulonglong2& wa, ulonglong2& wb) {
    u2p wr = (u2p)wrow; wa = wr[0]; wb = wr[1];
}

// ---------------------------------------------------------------------------
__global__ void zero_kernel(int n4) {
    int i = blockIdx.x * blockDim.x + threadIdx.x;
    if (i < n4) ((float4*)g_agg)[i] = make_float4(0.f, 0.f, 0.f, 0.f);
}

// ---------------------------------------------------------------------------
// P = node_feats @ msg_w1[0:128,:]. 128 rows/block, 512 thr (4 rows x 8 cols)
__global__ __launch_bounds__(512, 1) void p_kernel(
    const float* __restrict__ nf, const float* __restrict__ w1, int N)
{
    extern __shared__ float sm[];
    float* sw = sm;          // 128*128
    float* sa = sm + 16384;  // 128 k * 132 (k-major)
    int tid = threadIdx.x;
    int n0 = blockIdx.x * 128;

    for (int i = tid; i < 4096; i += 512)
        ((float4*)sw)[i] = ((const float4*)w1)[i];
    for (int i = tid; i < 4096; i += 512) {
        int r = i & 127, j = i >> 7, gn = n0 + r;
        float4 v = (gn < N) ? ((const float4*)nf)[(size_t)gn * 32 + j]
                            : make_float4(0.f, 0.f, 0.f, 0.f);
        sa[(4 * j + 0) * 132 + r] = v.x;
        sa[(4 * j + 1) * 132 + r] = v.y;
        sa[(4 * j + 2) * 132 + r] = v.z;
        sa[(4 * j + 3) * 132 + r] = v.w;
    }
    __syncthreads();

    int q = tid & 31, c0 = (tid >> 5) * 8, rb = 4 * q;
    ull acc[16];
#pragma unroll
    for (int i = 0; i < 16; i++) acc[i] = pack2(0.f, 0.f);

    float4 a = *(float4*)(sa + rb);
    ulonglong2 wa, wb; ldw(sw + c0, wa, wb);
#pragma unroll 4
    for (int k = 0; k < 128; k++) {
        float4 an; ulonglong2 wan, wbn;
        if (k + 1 < 128) {
            an = *(float4*)(sa + (k + 1) * 132 + rb);
            ldw(sw + (k + 1) * ND + c0, wan, wbn);
        }
        fma_row8w(acc + 0,  pack2(a.x, a.x), wa, wb);
        fma_row8w(acc + 4,  pack2(a.y, a.y), wa, wb);
        fma_row8w(acc + 8,  pack2(a.z, a.z), wa, wb);
        fma_row8w(acc + 12, pack2(a.w, a.w), wa, wb);
        a = an; wa = wan; wb = wbn;
    }
#pragma unroll
    for (int j = 0; j < 4; j++) {
        int gn = n0 + rb + j;
        if (gn < N) {
            float4* pr = (float4*)(g_P + (size_t)gn * ND + c0);
#pragma unroll
            for (int i = 0; i < 2; i++) {
                float x, y, z, w_;
                unpack2(acc[j * 4 + 2 * i], x, y);
                unpack2(acc[j * 4 + 2 * i + 1], z, w_);
                pr[i] = make_float4(x, y, z, w_);
            }
        }
    }
}

// ---------------------------------------------------------------------------
// Fused edge kernel. 128 edges/block, 512 thr (4 edges x 8 cols).
__global__ __launch_bounds__(512, 1) void edge_kernel(
    const float* __restrict__ ef,
    const float* __restrict__ w1, const float* __restrict__ b1,
    const float* __restrict__ w2, const float* __restrict__ b2,
    const int* __restrict__ eidx, int N, int E)
{
    extern __shared__ float sm[];
    float* sw1e = sm;                 // 64*128   = 8192
    float* sw2  = sm + 8192;          // 128*128  = 16384
    float* sb1  = sm + 24576;         // 128
    float* sb2  = sm + 24704;         // 128
    float* seft = sm + 24832;         // 64 k * 132 = 8448  (k-major)
    float* sht  = sm + 33280;         // 128 k * 132 = 16896 (k-major)
    int*   ssrc = (int*)(sm + 50176); // 128
    int*   sdst = ssrc + 128;         // 128

    int tid = threadIdx.x;
    int e0 = blockIdx.x * TE;

    for (int i = tid; i < 2048; i += 512)
        ((float4*)sw1e)[i] = ((const float4*)(w1 + 128 * ND))[i];
    for (int i = tid; i < 4096; i += 512)
        ((float4*)sw2)[i] = ((const float4*)w2)[i];
    if (tid < 32)       ((float4*)sb1)[tid]      = ((const float4*)b1)[tid];
    else if (tid < 64)  ((float4*)sb2)[tid - 32] = ((const float4*)b2)[tid - 32];
    if (tid < TE) {
        int ge = e0 + tid;
        if (ge < E) {
            int s = eidx[ge], d = eidx[E + ge];
            ssrc[tid] = ((unsigned)s < (unsigned)N) ? s : -1;
            sdst[tid] = ((unsigned)d < (unsigned)N) ? d : 0;
        } else { ssrc[tid] = -1; sdst[tid] = 0; }
    }
    for (int i = tid; i < 2048; i += 512) {
        int r = i & 127, j = i >> 7, ge = e0 + r;
        float4 v = (ge < E) ? ((const float4*)ef)[(size_t)ge * 16 + j]
                            : make_float4(0.f, 0.f, 0.f, 0.f);
        seft[(4 * j + 0) * 132 + r] = v.x;
        seft[(4 * j + 1) * 132 + r] = v.y;
        seft[(4 * j + 2) * 132 + r] = v.z;
        seft[(4 * j + 3) * 132 + r] = v.w;
    }
    __syncthreads();

    int q = tid & 31, c0 = (tid >> 5) * 8, eb = 4 * q;

    // phase A: h = lrelu(P[dst] + ef @ w1e + b1), K=64
    ull acc[16];
#pragma unroll
    for (int i = 0; i < 16; i++) acc[i] = pack2(0.f, 0.f);
    {
        float4 a = *(float4*)(seft + eb);
        ulonglong2 wa, wb; ldw(sw1e + c0, wa, wb);
#pragma unroll 4
        for (int k = 0; k < 64; k++) {
            float4 an; ulonglong2 wan, wbn;
            if (k + 1 < 64) {
                an = *(float4*)(seft + (k + 1) * 132 + eb);
                ldw(sw1e + (k + 1) * ND + c0, wan, wbn);
            }
            fma_row8w(acc + 0,  pack2(a.x, a.x), wa, wb);
            fma_row8w(acc + 4,  pack2(a.y, a.y), wa, wb);
            fma_row8w(acc + 8,  pack2(a.z, a.z), wa, wb);
            fma_row8w(acc + 12, pack2(a.w, a.w), wa, wb);
            a = an; wa = wan; wb = wbn;
        }
    }
    float hh[4][8];
    {
        const float4* br = (const float4*)(sb1 + c0);
        float4 bb0 = br[0], bb1 = br[1];
#pragma unroll
        for (int j = 0; j < 4; j++) {
            int d = sdst[eb + j];
            const float4* pr = (const float4*)(g_P + (size_t)d * ND + c0);
            float4 p0 = pr[0], p1 = pr[1];
            float x, y, z, w_;
            unpack2(acc[j * 4 + 0], x, y);
            unpack2(acc[j * 4 + 1], z, w_);
            hh[j][0] = lrelu(x + p0.x + bb0.x);
            hh[j][1] = lrelu(y + p0.y + bb0.y);
            hh[j][2] = lrelu(z + p0.z + bb0.z);
            hh[j][3] = lrelu(w_ + p0.w + bb0.w);
            unpack2(acc[j * 4 + 2], x, y);
            unpack2(acc[j * 4 + 3], z, w_);
            hh[j][4] = lrelu(x + p1.x + bb1.x);
            hh[j][5] = lrelu(y + p1.y + bb1.y);
            hh[j][6] = lrelu(z + p1.z + bb1.z);
            hh[j][7] = lrelu(w_ + p1.w + bb1.w);
        }
    }
    // transposed store: sht[c][edge], 4 edges per float4
#pragma unroll
    for (int c = 0; c < 8; c++)
        *(float4*)(sht + (c0 + c) * 132 + eb) =
            make_float4(hh[0][c], hh[1][c], hh[2][c], hh[3][c]);
    __syncthreads();

    // phase B: messages = h @ w2 + b2, K=128, scatter
#pragma unroll
    for (int i = 0; i < 16; i++) acc[i] = pack2(0.f, 0.f);
    {
        float4 a = *(float4*)(sht + eb);
        ulonglong2 wa, wb; ldw(sw2 + c0, wa, wb);
#pragma unroll 4
        for (int k = 0; k < 128; k++) {
            float4 an; ulonglong2 wan, wbn;
            if (k + 1 < 128) {
                an = *(float4*)(sht + (k + 1) * 132 + eb);
                ldw(sw2 + (k + 1) * ND + c0, wan, wbn);
            }
            fma_row8w(acc + 0,  pack2(a.x, a.x), wa, wb);
            fma_row8w(acc + 4,  pack2(a.y, a.y), wa, wb);
            fma_row8w(acc + 8,  pack2(a.z, a.z), wa, wb);
            fma_row8w(acc + 12, pack2(a.w, a.w), wa, wb);
            a = an; wa = wan; wb = wbn;
        }
    }
    {
        const float4* br = (const float4*)(sb2 + c0);
        float4 bb0 = br[0], bb1 = br[1];
#pragma unroll
        for (int j = 0; j < 4; j++) {
            int s = ssrc[eb + j];
            if (s >= 0) {
                float* ar = g_agg + (size_t)s * ND + c0;
                float x, y, z, w_;
                unpack2(acc[j * 4 + 0], x, y);
                unpack2(acc[j * 4 + 1], z, w_);
                x += bb0.x; y += bb0.y; z += bb0.z; w_ += bb0.w;
                asm volatile("red.global.add.v4.f32 [%0], {%1, %2, %3, %4};"
                    :: "l"(ar), "f"(x), "f"(y), "f"(z), "f"(w_) : "memory");
                unpack2(acc[j * 4 + 2], x, y);
                unpack2(acc[j * 4 + 3], z, w_);
                x += bb1.x; y += bb1.y; z += bb1.z; w_ += bb1.w;
                asm volatile("red.global.add.v4.f32 [%0], {%1, %2, %3, %4};"
                    :: "l"(ar + 4), "f"(x), "f"(y), "f"(z), "f"(w_) : "memory");
            }
        }
    }
}

// ---------------------------------------------------------------------------
// H2 = lrelu([nf, agg] @ upd_w1 + ub1). 64 rows/block, 512 thr (2 rows x 8 cols)
__global__ __launch_bounds__(512, 1) void upd1_kernel(
    const float* __restrict__ nf, const float* __restrict__ w1,
    const float* __restrict__ b1, int N)
{
    extern __shared__ float sm[];
    float* sw = sm;          // 256*128 = 32768
    float* sa = sm + 32768;  // 256 k * 68 = 17408
    int tid = threadIdx.x;
    int n0 = blockIdx.x * 64;

    for (int i = tid; i < 8192; i += 512)
        ((float4*)sw)[i] = ((const float4*)w1)[i];
    for (int i = tid; i < 2048; i += 512) {
        int r = i & 63, j = i >> 6, gn = n0 + r;
        float4 v = (gn < N) ? ((const float4*)nf)[(size_t)gn * 32 + j]
                            : make_float4(0.f, 0.f, 0.f, 0.f);
        float4 u = (gn < N) ? ((const float4*)g_agg)[(size_t)gn * 32 + j]
                            : make_float4(0.f, 0.f, 0.f, 0.f);
        sa[(4 * j + 0) * 68 + r] = v.x;
        sa[(4 * j + 1) * 68 + r] = v.y;
        sa[(4 * j + 2) * 68 + r] = v.z;
        sa[(4 * j + 3) * 68 + r] = v.w;
        sa[(128 + 4 * j + 0) * 68 + r] = u.x;
        sa[(128 + 4 * j + 1) * 68 + r] = u.y;
        sa[(128 + 4 * j + 2) * 68 + r] = u.z;
        sa[(128 + 4 * j + 3) * 68 + r] = u.w;
    }
    __syncthreads();

    int q = tid & 31, c0 = (tid >> 5) * 8, rb = 2 * q;
    ull acc[8];
#pragma unroll
    for (int i = 0; i < 8; i++) acc[i] = pack2(0.f, 0.f);

    float2 a = *(float2*)(sa + rb);
    ulonglong2 wa, wb; ldw(sw + c0, wa, wb);
#pragma unroll 4
    for (int k = 0; k < 256; k++) {
        float2 an; ulonglong2 wan, wbn;
        if (k + 1 < 256) {
            an = *(float2*)(sa + (k + 1) * 68 + rb);
            ldw(sw + (k + 1) * ND + c0, wan, wbn);
        }
        fma_row8w(acc + 0, pack2(a.x, a.x), wa, wb);
        fma_row8w(acc + 4, pack2(a.y, a.y), wa, wb);
        a = an; wa = wan; wb = wbn;
    }
    {
        const float4* br = (const float4*)(b1 + c0);
        float4 bb0 = __ldg(br), bb1 = __ldg(br + 1);
#pragma unroll
        for (int j = 0; j < 2; j++) {
            int gn = n0 + rb + j;
            if (gn < N) {
                float4* hr = (float4*)(g_H2 + (size_t)gn * ND + c0);
                float x, y, z, w_;
                unpack2(acc[j * 4 + 0], x, y);
                unpack2(acc[j * 4 + 1], z, w_);
                hr[0] = make_float4(lrelu(x + bb0.x), lrelu(y + bb0.y),
                                    lrelu(z + bb0.z), lrelu(w_ + bb0.w));
                unpack2(acc[j * 4 + 2], x, y);
                unpack2(acc[j * 4 + 3], z, w_);
                hr[1] = make_float4(lrelu(x + bb1.x), lrelu(y + bb1.y),
                                    lrelu(z + bb1.z), lrelu(w_ + bb1.w));
            }
        }
    }
}

// ---------------------------------------------------------------------------
// out = H2 @ upd_w2 + ub2. 128 rows/block, 512 thr (4 rows x 8 cols)
__global__ __launch_bounds__(512, 1) void upd2_kernel(
    const float* __restrict__ w2, const float* __restrict__ b2,
    float* __restrict__ out, int N)
{
    extern __shared__ float sm[];
    float* sw = sm;          // 128*128
    float* sa = sm + 16384;  // 128 k * 132
    int tid = threadIdx.x;
    int n0 = blockIdx.x * 128;

    for (int i = tid; i < 4096; i += 512)
        ((float4*)sw)[i] = ((const float4*)w2)[i];
    for (int i = tid; i < 4096; i += 512) {
        int r = i & 127, j = i >> 7, gn = n0 + r;
        float4 v = (gn < N) ? ((const float4*)g_H2)[(size_t)gn * 32 + j]
                            : make_float4(0.f, 0.f, 0.f, 0.f);
        sa[(4 * j + 0) * 132 + r] = v.x;
        sa[(4 * j + 1) * 132 + r] = v.y;
        sa[(4 * j + 2) * 132 + r] = v.z;
        sa[(4 * j + 3) * 132 + r] = v.w;
    }
    __syncthreads();

    int q = tid & 31, c0 = (tid >> 5) * 8, rb = 4 * q;
    ull acc[16];
#pragma unroll
    for (int i = 0; i < 16; i++) acc[i] = pack2(0.f, 0.f);

    float4 a = *(float4*)(sa + rb);
    ulonglong2 wa, wb; ldw(sw + c0, wa, wb);
#pragma unroll 4
    for (int k = 0; k < 128; k++) {
        float4 an; ulonglong2 wan, wbn;
        if (k + 1 < 128) {
            an = *(float4*)(sa + (k + 1) * 132 + rb);
            ldw(sw + (k + 1) * ND + c0, wan, wbn);
        }
        fma_row8w(acc + 0,  pack2(a.x, a.x), wa, wb);
        fma_row8w(acc + 4,  pack2(a.y, a.y), wa, wb);
        fma_row8w(acc + 8,  pack2(a.z, a.z), wa, wb);
        fma_row8w(acc + 12, pack2(a.w, a.w), wa, wb);
        a = an; wa = wan; wb = wbn;
    }
    {
        const float4* br = (const float4*)(b2 + c0);
        float4 bb0 = __ldg(br), bb1 = __ldg(br + 1);
#pragma unroll
        for (int j = 0; j < 4; j++) {
            int gn = n0 + rb + j;
            if (gn < N) {
                float4* orow = (float4*)(out + (size_t)gn * ND + c0);
                float x, y, z, w_;
                unpack2(acc[j * 4 + 0], x, y);
                unpack2(acc[j * 4 + 1], z, w_);
                orow[0] = make_float4(x + bb0.x, y + bb0.y, z + bb0.z, w_ + bb0.w);
                unpack2(acc[j * 4 + 2], x, y);
                unpack2(acc[j * 4 + 3], z, w_);
                orow[1] = make_float4(x + bb1.x, y + bb1.y, z + bb1.z, w_ + bb1.w);
            }
        }
    }
}

// ---------------------------------------------------------------------------
extern "C" void kernel_launch(void* const* d_in, const int* in_sizes, int n_in,
                              void* d_out, int out_size)
{
    const float* nf  = (const float*)d_in[0];
    const float* ef  = (const float*)d_in[1];
    const float* mw1 = (const float*)d_in[2];
    const float* mb1 = (const float*)d_in[3];
    const float* mw2 = (const float*)d_in[4];
    const float* mb2 = (const float*)d_in[5];
    const float* uw1 = (const float*)d_in[6];
    const float* ub1 = (const float*)d_in[7];
    const float* uw2 = (const float*)d_in[8];
    const float* ub2 = (const float*)d_in[9];
    const int* eidx  = (const int*)d_in[10];   // int32 (JAX x64 disabled)
    float* out = (float*)d_out;

    int N = in_sizes[0] / ND;
    int E = in_sizes[10] / 2;

    const int P_SM  = (16384 + 128 * 132) * 4;            // 133120
    const int E_SM  = (50176 + 256) * 4;                  // 201728
    const int U1_SM = (32768 + 256 * 68) * 4;             // 200704
    const int U2_SM = (16384 + 128 * 132) * 4;            // 133120

    cudaFuncSetAttribute(p_kernel,    cudaFuncAttributeMaxDynamicSharedMemorySize, P_SM);
    cudaFuncSetAttribute(edge_kernel, cudaFuncAttributeMaxDynamicSharedMemorySize, E_SM);
    cudaFuncSetAttribute(upd1_kernel, cudaFuncAttributeMaxDynamicSharedMemorySize, U1_SM);
    cudaFuncSetAttribute(upd2_kernel, cudaFuncAttributeMaxDynamicSharedMemorySize, U2_SM);

    int n4 = (N * ND) / 4;
    zero_kernel<<<(n4 + 255) / 256, 256>>>(n4);
    p_kernel<<<(N + 127) / 128, 512, P_SM>>>(nf, mw1, N);
    edge_kernel<<<(E + TE - 1) / TE, 512, E_SM>>>(ef, mw1, mb1, mw2, mb2, eidx, N, E);
    upd1_kernel<<<(N + 63) / 64, 512, U1_SM>>>(nf, uw1, ub1, N);
    upd2_kernel<<<(N + 127) / 128, 512, U2_SM>>>(uw2, ub2, out, N);
}

// round 14
// speedup vs baseline: 1.1524x; 1.0771x over previous
#include <cuda_runtime.h>

#define ND 128
#define TE 128
#define MAXN 50000

typedef unsigned long long ull;
typedef const ulonglong2* u2p;

__device__ __align__(256) float g_P[MAXN * ND];
__device__ __align__(256) float g_agg[MAXN * ND];
__device__ __align__(256) float g_H2[MAXN * ND];

__device__ __forceinline__ ull pack2(float x, float y) {
    ull r; asm("mov.b64 %0, {%1, %2};" : "=l"(r) : "f"(x), "f"(y)); return r;
}
__device__ __forceinline__ void unpack2(ull v, float& x, float& y) {
    asm("mov.b64 {%0, %1}, %2;" : "=f"(x), "=f"(y) : "l"(v));
}
__device__ __forceinline__ void fma2(ull& acc, ull a, ull b) {
    asm("fma.rn.f32x2 %0, %1, %2, %0;" : "+l"(acc) : "l"(a), "l"(b));
}
__device__ __forceinline__ float lrelu(float x) { return x >= 0.f ? x : 0.2f * x; }

__device__ __forceinline__ void fma_row8w(ull* acc, ull a2, ulonglong2 wa, ulonglong2 wb) {
    fma2(acc[0], a2, wa.x); fma2(acc[1], a2, wa.y);
    fma2(acc[2], a2, wb.x); fma2(acc[3], a2, wb.y);
}
__device__ __forceinline__ void ldw(const float* wrow, ulonglong2& wa, ulonglong2& wb) {
    u2p wr = (u2p)wrow; wa = wr[0]; wb = wr[1];
}

// ---------------------------------------------------------------------------
__global__ void zero_kernel(int n4) {
    int i = blockIdx.x * blockDim.x + threadIdx.x;
    if (i < n4) ((float4*)g_agg)[i] = make_float4(0.f, 0.f, 0.f, 0.f);
}

// ---------------------------------------------------------------------------
// P = node_feats @ msg_w1[0:128,:]. 128 rows/block, 512 thr (4 rows x 8 cols)
__global__ __launch_bounds__(512, 1) void p_kernel(
    const float* __restrict__ nf, const float* __restrict__ w1, int N)
{
    extern __shared__ float sm[];
    float* sw = sm;          // 128*128
    float* sa = sm + 16384;  // 128 k * 132 (k-major)
    int tid = threadIdx.x;
    int n0 = blockIdx.x * 128;

    for (int i = tid; i < 4096; i += 512)
        ((float4*)sw)[i] = ((const float4*)w1)[i];
    for (int i = tid; i < 4096; i += 512) {
        int r = i & 127, j = i >> 7, gn = n0 + r;
        float4 v = (gn < N) ? ((const float4*)nf)[(size_t)gn * 32 + j]
                            : make_float4(0.f, 0.f, 0.f, 0.f);
        sa[(4 * j + 0) * 132 + r] = v.x;
        sa[(4 * j + 1) * 132 + r] = v.y;
        sa[(4 * j + 2) * 132 + r] = v.z;
        sa[(4 * j + 3) * 132 + r] = v.w;
    }
    __syncthreads();

    int q = tid & 31, c0 = (tid >> 5) * 8, rb = 4 * q;
    ull acc[16];
#pragma unroll
    for (int i = 0; i < 16; i++) acc[i] = pack2(0.f, 0.f);

    const float* ap = sa + rb;
    const float* wp = sw + c0;
    float4 a = *(const float4*)ap;
    ulonglong2 wa, wb; ldw(wp, wa, wb);
#pragma unroll 4
    for (int k = 0; k < 127; k++) {
        ap += 132; wp += ND;
        float4 an = *(const float4*)ap;
        ulonglong2 wan, wbn; ldw(wp, wan, wbn);
        fma_row8w(acc + 0,  pack2(a.x, a.x), wa, wb);
        fma_row8w(acc + 4,  pack2(a.y, a.y), wa, wb);
        fma_row8w(acc + 8,  pack2(a.z, a.z), wa, wb);
        fma_row8w(acc + 12, pack2(a.w, a.w), wa, wb);
        a = an; wa = wan; wb = wbn;
    }
    fma_row8w(acc + 0,  pack2(a.x, a.x), wa, wb);
    fma_row8w(acc + 4,  pack2(a.y, a.y), wa, wb);
    fma_row8w(acc + 8,  pack2(a.z, a.z), wa, wb);
    fma_row8w(acc + 12, pack2(a.w, a.w), wa, wb);

#pragma unroll
    for (int j = 0; j < 4; j++) {
        int gn = n0 + rb + j;
        if (gn < N) {
            float4* pr = (float4*)(g_P + (size_t)gn * ND + c0);
#pragma unroll
            for (int i = 0; i < 2; i++) {
                float x, y, z, w_;
                unpack2(acc[j * 4 + 2 * i], x, y);
                unpack2(acc[j * 4 + 2 * i + 1], z, w_);
                pr[i] = make_float4(x, y, z, w_);
            }
        }
    }
}

// ---------------------------------------------------------------------------
// Fused edge kernel. 128 edges/block, 512 thr (4 edges x 8 cols).
__global__ __launch_bounds__(512, 1) void edge_kernel(
    const float* __restrict__ ef,
    const float* __restrict__ w1, const float* __restrict__ b1,
    const float* __restrict__ w2, const float* __restrict__ b2,
    const int* __restrict__ eidx, int N, int E)
{
    extern __shared__ float sm[];
    float* sw1e = sm;                 // 64*128   = 8192
    float* sw2  = sm + 8192;          // 128*128  = 16384
    float* sb1  = sm + 24576;         // 128
    float* sb2  = sm + 24704;         // 128
    float* seft = sm + 24832;         // 64 k * 132 = 8448  (k-major)
    float* sht  = sm + 33280;         // 128 k * 132 = 16896 (k-major)
    int*   ssrc = (int*)(sm + 50176); // 128
    int*   sdst = ssrc + 128;         // 128

    int tid = threadIdx.x;
    int e0 = blockIdx.x * TE;

    for (int i = tid; i < 2048; i += 512)
        ((float4*)sw1e)[i] = ((const float4*)(w1 + 128 * ND))[i];
    for (int i = tid; i < 4096; i += 512)
        ((float4*)sw2)[i] = ((const float4*)w2)[i];
    if (tid < 32)       ((float4*)sb1)[tid]      = ((const float4*)b1)[tid];
    else if (tid < 64)  ((float4*)sb2)[tid - 32] = ((const float4*)b2)[tid - 32];
    if (tid < TE) {
        int ge = e0 + tid;
        if (ge < E) {
            int s = eidx[ge], d = eidx[E + ge];
            ssrc[tid] = ((unsigned)s < (unsigned)N) ? s : -1;
            sdst[tid] = ((unsigned)d < (unsigned)N) ? d : 0;
        } else { ssrc[tid] = -1; sdst[tid] = 0; }
    }
    for (int i = tid; i < 2048; i += 512) {
        int r = i & 127, j = i >> 7, ge = e0 + r;
        float4 v = (ge < E) ? ((const float4*)ef)[(size_t)ge * 16 + j]
                            : make_float4(0.f, 0.f, 0.f, 0.f);
        seft[(4 * j + 0) * 132 + r] = v.x;
        seft[(4 * j + 1) * 132 + r] = v.y;
        seft[(4 * j + 2) * 132 + r] = v.z;
        seft[(4 * j + 3) * 132 + r] = v.w;
    }
    __syncthreads();

    int q = tid & 31, c0 = (tid >> 5) * 8, eb = 4 * q;

    // phase A: h = lrelu(P[dst] + ef @ w1e + b1), K=64
    ull acc[16];
#pragma unroll
    for (int i = 0; i < 16; i++) acc[i] = pack2(0.f, 0.f);
    {
        const float* ap = seft + eb;
        const float* wp = sw1e + c0;
        float4 a = *(const float4*)ap;
        ulonglong2 wa, wb; ldw(wp, wa, wb);
#pragma unroll 4
        for (int k = 0; k < 63; k++) {
            ap += 132; wp += ND;
            float4 an = *(const float4*)ap;
            ulonglong2 wan, wbn; ldw(wp, wan, wbn);
            fma_row8w(acc + 0,  pack2(a.x, a.x), wa, wb);
            fma_row8w(acc + 4,  pack2(a.y, a.y), wa, wb);
            fma_row8w(acc + 8,  pack2(a.z, a.z), wa, wb);
            fma_row8w(acc + 12, pack2(a.w, a.w), wa, wb);
            a = an; wa = wan; wb = wbn;
        }
        fma_row8w(acc + 0,  pack2(a.x, a.x), wa, wb);
        fma_row8w(acc + 4,  pack2(a.y, a.y), wa, wb);
        fma_row8w(acc + 8,  pack2(a.z, a.z), wa, wb);
        fma_row8w(acc + 12, pack2(a.w, a.w), wa, wb);
    }
    float hh[4][8];
    {
        const float4* br = (const float4*)(sb1 + c0);
        float4 bb0 = br[0], bb1 = br[1];
#pragma unroll
        for (int j = 0; j < 4; j++) {
            int d = sdst[eb + j];
            const float4* pr = (const float4*)(g_P + (size_t)d * ND + c0);
            float4 p0 = pr[0], p1 = pr[1];
            float x, y, z, w_;
            unpack2(acc[j * 4 + 0], x, y);
            unpack2(acc[j * 4 + 1], z, w_);
            hh[j][0] = lrelu(x + p0.x + bb0.x);
            hh[j][1] = lrelu(y + p0.y + bb0.y);
            hh[j][2] = lrelu(z + p0.z + bb0.z);
            hh[j][3] = lrelu(w_ + p0.w + bb0.w);
            unpack2(acc[j * 4 + 2], x, y);
            unpack2(acc[j * 4 + 3], z, w_);
            hh[j][4] = lrelu(x + p1.x + bb1.x);
            hh[j][5] = lrelu(y + p1.y + bb1.y);
            hh[j][6] = lrelu(z + p1.z + bb1.z);
            hh[j][7] = lrelu(w_ + p1.w + bb1.w);
        }
    }
#pragma unroll
    for (int c = 0; c < 8; c++)
        *(float4*)(sht + (c0 + c) * 132 + eb) =
            make_float4(hh[0][c], hh[1][c], hh[2][c], hh[3][c]);
    __syncthreads();

    // phase B: messages = h @ w2 + b2, K=128, scatter
#pragma unroll
    for (int i = 0; i < 16; i++) acc[i] = pack2(0.f, 0.f);
    {
        const float* ap = sht + eb;
        const float* wp = sw2 + c0;
        float4 a = *(const float4*)ap;
        ulonglong2 wa, wb; ldw(wp, wa, wb);
#pragma unroll 4
        for (int k = 0; k < 127; k++) {
            ap += 132; wp += ND;
            float4 an = *(const float4*)ap;
            ulonglong2 wan, wbn; ldw(wp, wan, wbn);
            fma_row8w(acc + 0,  pack2(a.x, a.x), wa, wb);
            fma_row8w(acc + 4,  pack2(a.y, a.y), wa, wb);
            fma_row8w(acc + 8,  pack2(a.z, a.z), wa, wb);
            fma_row8w(acc + 12, pack2(a.w, a.w), wa, wb);
            a = an; wa = wan; wb = wbn;
        }
        fma_row8w(acc + 0,  pack2(a.x, a.x), wa, wb);
        fma_row8w(acc + 4,  pack2(a.y, a.y), wa, wb);
        fma_row8w(acc + 8,  pack2(a.z, a.z), wa, wb);
        fma_row8w(acc + 12, pack2(a.w, a.w), wa, wb);
    }
    {
        const float4* br = (const float4*)(sb2 + c0);
        float4 bb0 = br[0], bb1 = br[1];
#pragma unroll
        for (int j = 0; j < 4; j++) {
            int s = ssrc[eb + j];
            if (s >= 0) {
                float* ar = g_agg + (size_t)s * ND + c0;
                float x, y, z, w_;
                unpack2(acc[j * 4 + 0], x, y);
                unpack2(acc[j * 4 + 1], z, w_);
                x += bb0.x; y += bb0.y; z += bb0.z; w_ += bb0.w;
                asm volatile("red.global.add.v4.f32 [%0], {%1, %2, %3, %4};"
                    :: "l"(ar), "f"(x), "f"(y), "f"(z), "f"(w_) : "memory");
                unpack2(acc[j * 4 + 2], x, y);
                unpack2(acc[j * 4 + 3], z, w_);
                x += bb1.x; y += bb1.y; z += bb1.z; w_ += bb1.w;
                asm volatile("red.global.add.v4.f32 [%0], {%1, %2, %3, %4};"
                    :: "l"(ar + 4), "f"(x), "f"(y), "f"(z), "f"(w_) : "memory");
            }
        }
    }
}

// ---------------------------------------------------------------------------
// H2 = lrelu([nf, agg] @ upd_w1 + ub1). 64 rows/block, 512 thr (2 rows x 8 cols)
__global__ __launch_bounds__(512, 1) void upd1_kernel(
    const float* __restrict__ nf, const float* __restrict__ w1,
    const float* __restrict__ b1, int N)
{
    extern __shared__ float sm[];
    float* sw = sm;          // 256*128 = 32768
    float* sa = sm + 32768;  // 256 k * 68 = 17408
    int tid = threadIdx.x;
    int n0 = blockIdx.x * 64;

    for (int i = tid; i < 8192; i += 512)
        ((float4*)sw)[i] = ((const float4*)w1)[i];
    for (int i = tid; i < 2048; i += 512) {
        int r = i & 63, j = i >> 6, gn = n0 + r;
        float4 v = (gn < N) ? ((const float4*)nf)[(size_t)gn * 32 + j]
                            : make_float4(0.f, 0.f, 0.f, 0.f);
        float4 u = (gn < N) ? ((const float4*)g_agg)[(size_t)gn * 32 + j]
                            : make_float4(0.f, 0.f, 0.f, 0.f);
        sa[(4 * j + 0) * 68 + r] = v.x;
        sa[(4 * j + 1) * 68 + r] = v.y;
        sa[(4 * j + 2) * 68 + r] = v.z;
        sa[(4 * j + 3) * 68 + r] = v.w;
        sa[(128 + 4 * j + 0) * 68 + r] = u.x;
        sa[(128 + 4 * j + 1) * 68 + r] = u.y;
        sa[(128 + 4 * j + 2) * 68 + r] = u.z;
        sa[(128 + 4 * j + 3) * 68 + r] = u.w;
    }
    __syncthreads();

    int q = tid & 31, c0 = (tid >> 5) * 8, rb = 2 * q;
    ull acc[8];
#pragma unroll
    for (int i = 0; i < 8; i++) acc[i] = pack2(0.f, 0.f);

    const float* ap = sa + rb;
    const float* wp = sw + c0;
    float2 a = *(const float2*)ap;
    ulonglong2 wa, wb; ldw(wp, wa, wb);
#pragma unroll 8
    for (int k = 0; k < 255; k++) {
        ap += 68; wp += ND;
        float2 an = *(const float2*)ap;
        ulonglong2 wan, wbn; ldw(wp, wan, wbn);
        fma_row8w(acc + 0, pack2(a.x, a.x), wa, wb);
        fma_row8w(acc + 4, pack2(a.y, a.y), wa, wb);
        a = an; wa = wan; wb = wbn;
    }
    fma_row8w(acc + 0, pack2(a.x, a.x), wa, wb);
    fma_row8w(acc + 4, pack2(a.y, a.y), wa, wb);
    {
        const float4* br = (const float4*)(b1 + c0);
        float4 bb0 = __ldg(br), bb1 = __ldg(br + 1);
#pragma unroll
        for (int j = 0; j < 2; j++) {
            int gn = n0 + rb + j;
            if (gn < N) {
                float4* hr = (float4*)(g_H2 + (size_t)gn * ND + c0);
                float x, y, z, w_;
                unpack2(acc[j * 4 + 0], x, y);
                unpack2(acc[j * 4 + 1], z, w_);
                hr[0] = make_float4(lrelu(x + bb0.x), lrelu(y + bb0.y),
                                    lrelu(z + bb0.z), lrelu(w_ + bb0.w));
                unpack2(acc[j * 4 + 2], x, y);
                unpack2(acc[j * 4 + 3], z, w_);
                hr[1] = make_float4(lrelu(x + bb1.x), lrelu(y + bb1.y),
                                    lrelu(z + bb1.z), lrelu(w_ + bb1.w));
            }
        }
    }
}

// ---------------------------------------------------------------------------
// out = H2 @ upd_w2 + ub2. 128 rows/block, 512 thr (4 rows x 8 cols)
__global__ __launch_bounds__(512, 1) void upd2_kernel(
    const float* __restrict__ w2, const float* __restrict__ b2,
    float* __restrict__ out, int N)
{
    extern __shared__ float sm[];
    float* sw = sm;          // 128*128
    float* sa = sm + 16384;  // 128 k * 132
    int tid = threadIdx.x;
    int n0 = blockIdx.x * 128;

    for (int i = tid; i < 4096; i += 512)
        ((float4*)sw)[i] = ((const float4*)w2)[i];
    for (int i = tid; i < 4096; i += 512) {
        int r = i & 127, j = i >> 7, gn = n0 + r;
        float4 v = (gn < N) ? ((const float4*)g_H2)[(size_t)gn * 32 + j]
                            : make_float4(0.f, 0.f, 0.f, 0.f);
        sa[(4 * j + 0) * 132 + r] = v.x;
        sa[(4 * j + 1) * 132 + r] = v.y;
        sa[(4 * j + 2) * 132 + r] = v.z;
        sa[(4 * j + 3) * 132 + r] = v.w;
    }
    __syncthreads();

    int q = tid & 31, c0 = (tid >> 5) * 8, rb = 4 * q;
    ull acc[16];
#pragma unroll
    for (int i = 0; i < 16; i++) acc[i] = pack2(0.f, 0.f);

    const float* ap = sa + rb;
    const float* wp = sw + c0;
    float4 a = *(const float4*)ap;
    ulonglong2 wa, wb; ldw(wp, wa, wb);
#pragma unroll 4
    for (int k = 0; k < 127; k++) {
        ap += 132; wp += ND;
        float4 an = *(const float4*)ap;
        ulonglong2 wan, wbn; ldw(wp, wan, wbn);
        fma_row8w(acc + 0,  pack2(a.x, a.x), wa, wb);
        fma_row8w(acc + 4,  pack2(a.y, a.y), wa, wb);
        fma_row8w(acc + 8,  pack2(a.z, a.z), wa, wb);
        fma_row8w(acc + 12, pack2(a.w, a.w), wa, wb);
        a = an; wa = wan; wb = wbn;
    }
    fma_row8w(acc + 0,  pack2(a.x, a.x), wa, wb);
    fma_row8w(acc + 4,  pack2(a.y, a.y), wa, wb);
    fma_row8w(acc + 8,  pack2(a.z, a.z), wa, wb);
    fma_row8w(acc + 12, pack2(a.w, a.w), wa, wb);
    {
        const float4* br = (const float4*)(b2 + c0);
        float4 bb0 = __ldg(br), bb1 = __ldg(br + 1);
#pragma unroll
        for (int j = 0; j < 4; j++) {
            int gn = n0 + rb + j;
            if (gn < N) {
                float4* orow = (float4*)(out + (size_t)gn * ND + c0);
                float x, y, z, w_;
                unpack2(acc[j * 4 + 0], x, y);
                unpack2(acc[j * 4 + 1], z, w_);
                orow[0] = make_float4(x + bb0.x, y + bb0.y, z + bb0.z, w_ + bb0.w);
                unpack2(acc[j * 4 + 2], x, y);
                unpack2(acc[j * 4 + 3], z, w_);
                orow[1] = make_float4(x + bb1.x, y + bb1.y, z + bb1.z, w_ + bb1.w);
            }
        }
    }
}

// ---------------------------------------------------------------------------
extern "C" void kernel_launch(void* const* d_in, const int* in_sizes, int n_in,
                              void* d_out, int out_size)
{
    const float* nf  = (const float*)d_in[0];
    const float* ef  = (const float*)d_in[1];
    const float* mw1 = (const float*)d_in[2];
    const float* mb1 = (const float*)d_in[3];
    const float* mw2 = (const float*)d_in[4];
    const float* mb2 = (const float*)d_in[5];
    const float* uw1 = (const float*)d_in[6];
    const float* ub1 = (const float*)d_in[7];
    const float* uw2 = (const float*)d_in[8];
    const float* ub2 = (const float*)d_in[9];
    const int* eidx  = (const int*)d_in[10];   // int32 (JAX x64 disabled)
    float* out = (float*)d_out;

    int N = in_sizes[0] / ND;
    int E = in_sizes[10] / 2;

    const int P_SM  = (16384 + 128 * 132) * 4;            // 133120
    const int E_SM  = (50176 + 256) * 4;                  // 201728
    const int U1_SM = (32768 + 256 * 68) * 4;             // 200704
    const int U2_SM = (16384 + 128 * 132) * 4;            // 133120

    cudaFuncSetAttribute(p_kernel,    cudaFuncAttributeMaxDynamicSharedMemorySize, P_SM);
    cudaFuncSetAttribute(edge_kernel, cudaFuncAttributeMaxDynamicSharedMemorySize, E_SM);
    cudaFuncSetAttribute(upd1_kernel, cudaFuncAttributeMaxDynamicSharedMemorySize, U1_SM);
    cudaFuncSetAttribute(upd2_kernel, cudaFuncAttributeMaxDynamicSharedMemorySize, U2_SM);

    int n4 = (N * ND) / 4;
    zero_kernel<<<(n4 + 255) / 256, 256>>>(n4);
    p_kernel<<<(N + 127) / 128, 512, P_SM>>>(nf, mw1, N);
    edge_kernel<<<(E + TE - 1) / TE, 512, E_SM>>>(ef, mw1, mb1, mw2, mb2, eidx, N, E);
    upd1_kernel<<<(N + 63) / 64, 512, U1_SM>>>(nf, uw1, ub1, N);
    upd2_kernel<<<(N + 127) / 128, 512, U2_SM>>>(uw2, ub2, out, N);
}